// round 4
// baseline (speedup 1.0000x reference)
#include <cuda_runtime.h>
#include <math.h>
#include <float.h>

#define A_N 33600
#define G_N 256
#define C_N 80
#define TOPK 10
#define NT   256
#define SPLIT 8
#define CHUNK (A_N / SPLIT)   // 4200
#define SENT 0xFFFFFFFFFFFFFFFFULL

// Scratch (allocation-free: __device__ globals)
__device__ float g_total_neg[A_N];
__device__ float g_clsT[C_N * A_N];
__device__ int   g_assigned[A_N];
__device__ unsigned long long g_pkeys[G_N * SPLIT * TOPK];
__device__ int   g_pcnt[G_N * SPLIT];

// monotone float -> uint mapping, packed with index: lexicographic (cost asc, idx asc)
__device__ __forceinline__ unsigned long long packKey(float v, unsigned idx) {
    unsigned u = __float_as_uint(v);
    u = (u & 0x80000000u) ? ~u : (u | 0x80000000u);
    return (((unsigned long long)u) << 32) | (unsigned long long)idx;
}

// ---- kernel 1: total_neg per anchor (+ init of g_assigned) ----
__global__ void totalneg_kernel(const float* __restrict__ scores) {
    int idx = blockIdx.x * blockDim.x + threadIdx.x;
    if (idx < A_N) g_assigned[idx] = -1;
    int warp = idx >> 5, lane = idx & 31;
    if (warp >= A_N) return;
    float sum = 0.0f;
    for (int c = lane; c < C_N; c += 32) {
        float x = scores[warp * C_N + c];
        sum += fmaxf(x, 0.0f) + log1pf(expf(-fabsf(x)));
    }
    for (int o = 16; o; o >>= 1) sum += __shfl_down_sync(0xffffffffu, sum, o);
    if (lane == 0) g_total_neg[warp] = sum;
}

// ---- kernel 2: transpose + fold softplus difference + total_neg ----
__global__ void clsT_kernel(const float* __restrict__ scores) {
    __shared__ float tile[32][33];
    int a0 = blockIdx.x * 32, c0 = blockIdx.y * 32;
    int a = a0 + threadIdx.y, c = c0 + threadIdx.x;
    float d = 0.0f;
    if (c < C_N) {
        float s = scores[a * C_N + c];
        float l = log1pf(expf(-fabsf(s)));
        float sp_pos = fmaxf(-s, 0.0f) + l;
        float sp_neg = fmaxf( s, 0.0f) + l;
        d = sp_pos - sp_neg;
    }
    tile[threadIdx.y][threadIdx.x] = d;
    __syncthreads();
    int ao = a0 + threadIdx.x, co = c0 + threadIdx.y;
    if (co < C_N)
        g_clsT[(size_t)co * A_N + ao] = g_total_neg[ao] + tile[threadIdx.x][threadIdx.y];
}

// ---- kernel 3a: per-(GT, split) partial top-10 + inside-count ----
__global__ __launch_bounds__(NT) void simota_part_kernel(
    const float* __restrict__ pred_bboxes,
    const float* __restrict__ anchor_points,
    const int*   __restrict__ gt_labels,
    const float* __restrict__ gt_bboxes)
{
    const int g   = blockIdx.x;
    const int sp  = blockIdx.y;
    const int tid = threadIdx.x;

    const float4 gb = ((const float4*)gt_bboxes)[g];
    const float gx1 = gb.x, gy1 = gb.y, gx2 = gb.z, gy2 = gb.w;
    const int   L   = gt_labels[g];

    const float cx = (gx1 + gx2) / 2.0f;
    const float cy = (gy1 + gy2) / 2.0f;
    const float rx = 2.5f * (gx2 - gx1);
    const float ry = 2.5f * (gy2 - gy1);
    const float clx = cx - rx, chx = cx + rx;
    const float cly = cy - ry, chy = cy + ry;
    const float area_g = (gx2 - gx1) * (gy2 - gy1);

    unsigned long long bk[TOPK];
#pragma unroll
    for (int j = 0; j < TOPK; j++) bk[j] = SENT;
    int cnt = 0;

    const float2* ap2  = (const float2*)anchor_points;
    const float4* pb4  = (const float4*)pred_bboxes;
    const float*  crow = g_clsT + (size_t)L * A_N;
    const int base = sp * CHUNK;
    const int end  = base + CHUNK;

    for (int a = base + tid; a < end; a += NT) {
        float2 ap  = __ldg(ap2 + a);
        float  cls = __ldg(crow + a);

        bool inside = (ap.x >= gx1) & (ap.x <= gx2) & (ap.y >= gy1) & (ap.y <= gy2)
                    & (ap.x >= clx) & (ap.x <= chx) & (ap.y >= cly) & (ap.y <= chy);

        // exact lower bound: cost >= cls + mask (3*iou_cost >= 0, rn-add monotone)
        float lb = __fadd_rn(cls, inside ? 0.0f : 1e10f);
        bool cand = packKey(lb, (unsigned)a) <= bk[TOPK - 1];

        if (inside || cand) {
            float4 pb = __ldg(pb4 + a);
            float w  = fmaxf(fminf(pb.z, gx2) - fmaxf(pb.x, gx1), 0.0f);
            float h  = fmaxf(fminf(pb.w, gy2) - fmaxf(pb.y, gy1), 0.0f);
            float ov = w * h;
            cnt += (inside && ov > 0.0f);
            if (cand) {
                float area_p = (pb.z - pb.x) * (pb.w - pb.y);
                float iou  = ov / (area_p + area_g - ov + 1e-6f);
                float iouc = -logf(fmaxf(iou, 1e-7f));
                float cost = __fadd_rn(__fadd_rn(cls, __fmul_rn(3.0f, iouc)),
                                       inside ? 0.0f : 1e10f);
                unsigned long long k = packKey(cost, (unsigned)a);
                if (k < bk[TOPK - 1]) {
                    bk[TOPK - 1] = k;
#pragma unroll
                    for (int j = TOPK - 1; j > 0; j--) {
                        bool sw = bk[j] < bk[j - 1];
                        unsigned long long lo = sw ? bk[j] : bk[j - 1];
                        unsigned long long hi = sw ? bk[j - 1] : bk[j];
                        bk[j - 1] = lo; bk[j] = hi;
                    }
                }
            }
        }
    }

    // ---- block merge: NT threads x sorted 10 -> partial sorted 10 ----
    __shared__ unsigned long long skeys[NT * TOPK];
    __shared__ unsigned long long swmin[NT / 32];
    __shared__ int scnt[NT / 32];
    __shared__ unsigned long long s_winner;

#pragma unroll
    for (int j = 0; j < TOPK; j++) skeys[tid * TOPK + j] = bk[j];

    int lane = tid & 31, wid = tid >> 5;
    int c = cnt;
    for (int o = 16; o; o >>= 1) c += __shfl_down_sync(0xffffffffu, c, o);
    if (lane == 0) scnt[wid] = c;
    __syncthreads();
    if (tid == 0) {
        int s = 0;
        for (int i = 0; i < NT / 32; i++) s += scnt[i];
        g_pcnt[g * SPLIT + sp] = s;
    }

    unsigned long long* pout = g_pkeys + (size_t)(g * SPLIT + sp) * TOPK;
    int p = 0;
    for (int r = 0; r < TOPK; r++) {
        unsigned long long candk = (p < TOPK) ? skeys[tid * TOPK + p] : SENT;
        unsigned long long m = candk;
        for (int o = 16; o; o >>= 1) {
            unsigned long long other = __shfl_down_sync(0xffffffffu, m, o);
            m = (other < m) ? other : m;
        }
        if (lane == 0) swmin[wid] = m;
        __syncthreads();
        if (tid == 0) {
            unsigned long long w = swmin[0];
            for (int i = 1; i < NT / 32; i++) if (swmin[i] < w) w = swmin[i];
            s_winner = w;
            pout[r] = w;
        }
        __syncthreads();
        if (candk == s_winner) p++;
    }
}

// ---- kernel 3b: merge SPLIT partials per GT, scatter assignments ----
__global__ void merge_kernel() {
    int g = blockIdx.x * blockDim.x + threadIdx.x;
    if (g >= G_N) return;

    const unsigned long long* lists = g_pkeys + (size_t)g * SPLIT * TOPK;
    int pos[SPLIT];
#pragma unroll
    for (int s = 0; s < SPLIT; s++) pos[s] = 0;

    int cnt = 0;
#pragma unroll
    for (int s = 0; s < SPLIT; s++) cnt += g_pcnt[g * SPLIT + s];
    int k = (cnt < 1) ? 1 : ((cnt > TOPK) ? TOPK : cnt);

    for (int r = 0; r < k; r++) {
        unsigned long long best = SENT; int bs = 0;
#pragma unroll
        for (int s = 0; s < SPLIT; s++) {
            unsigned long long v = (pos[s] < TOPK) ? lists[s * TOPK + pos[s]] : SENT;
            if (v < best) { best = v; bs = s; }
        }
        pos[bs]++;
        atomicMax(&g_assigned[(int)(best & 0xffffffffu)], g);
    }
}

// ---- kernel 4a: zero the scores region, coalesced float4 ----
__global__ void zero_scores_kernel(float* __restrict__ out) {
    int i = blockIdx.x * blockDim.x + threadIdx.x;
    const int n4 = (A_N * (C_N + 1)) / 4;   // 680400
    float4* p = (float4*)(out + (size_t)5 * A_N);
    if (i < n4) p[i] = make_float4(0.f, 0.f, 0.f, 0.f);
}

// ---- kernel 4b: labels + bboxes + one-hot scatter ----
__global__ void finalize_kernel(const float* __restrict__ pred_bboxes,
                                const int*   __restrict__ gt_labels,
                                const float* __restrict__ gt_bboxes,
                                float* __restrict__ out)
{
    int a = blockIdx.x * blockDim.x + threadIdx.x;
    if (a >= A_N) return;

    int  g    = g_assigned[a];
    bool pos  = (g >= 0);
    int  safe = pos ? g : 0;
    int  label = pos ? gt_labels[safe] : C_N;

    float4 gbx = ((const float4*)gt_bboxes)[safe];

    out[a] = (float)label;

    float4* ob = (float4*)(out + A_N);
    ob[a] = pos ? gbx : make_float4(0.f, 0.f, 0.f, 0.f);

    if (pos) {
        float4 pb = ((const float4*)pred_bboxes)[a];
        float w = fmaxf(fminf(pb.z, gbx.z) - fmaxf(pb.x, gbx.x), 0.0f);
        float h = fmaxf(fminf(pb.w, gbx.w) - fmaxf(pb.y, gbx.y), 0.0f);
        float ov = w * h;
        float area_p = (pb.z - pb.x) * (pb.w - pb.y);
        float area_g = (gbx.z - gbx.x) * (gbx.w - gbx.y);
        float iou = ov / (area_p + area_g - ov + 1e-6f);
        out[(size_t)5 * A_N + (size_t)a * (C_N + 1) + label] = iou;
    }
    // non-pos: scores[a][80] = 0.0, already zeroed
}

extern "C" void kernel_launch(void* const* d_in, const int* in_sizes, int n_in,
                              void* d_out, int out_size) {
    const float* pred_scores   = (const float*)d_in[0];
    const float* pred_bboxes   = (const float*)d_in[1];
    const float* anchor_points = (const float*)d_in[2];
    const int*   gt_labels     = (const int*)  d_in[3];
    const float* gt_bboxes     = (const float*)d_in[4];
    float* out = (float*)d_out;

    totalneg_kernel<<<(A_N * 32 + 255) / 256, 256>>>(pred_scores);
    clsT_kernel<<<dim3(A_N / 32, (C_N + 31) / 32), dim3(32, 32)>>>(pred_scores);
    zero_scores_kernel<<<((A_N * (C_N + 1)) / 4 + 255) / 256, 256>>>(out);
    simota_part_kernel<<<dim3(G_N, SPLIT), NT>>>(pred_bboxes, anchor_points,
                                                 gt_labels, gt_bboxes);
    merge_kernel<<<1, G_N>>>();
    finalize_kernel<<<(A_N + 255) / 256, 256>>>(pred_bboxes, gt_labels, gt_bboxes, out);
}

// round 5
// speedup vs baseline: 1.8248x; 1.8248x over previous
#include <cuda_runtime.h>
#include <math.h>
#include <float.h>

#define A_N 33600
#define G_N 256
#define C_N 80
#define TOPK 10
#define NT   256
#define CAP  4096
#define SENT 0xFFFFFFFFFFFFFFFFULL

// Scratch (allocation-free: __device__ globals)
__device__ float g_total_neg[A_N];
__device__ int   g_assigned[A_N];
__device__ int   g_pcount[G_N];
__device__ int   g_plist[G_N * CAP];

// monotone float -> uint mapping, packed with index: lexicographic (cost asc, idx asc)
__device__ __forceinline__ unsigned long long packKey(float v, unsigned idx) {
    unsigned u = __float_as_uint(v);
    u = (u & 0x80000000u) ? ~u : (u | 0x80000000u);
    return (((unsigned long long)u) << 32) | (unsigned long long)idx;
}

// softplus difference with the reference's exact rounding sequence
__device__ __forceinline__ float sp_diff(float s) {
    float l = log1pf(expf(-fabsf(s)));
    return (fmaxf(-s, 0.0f) + l) - (fmaxf(s, 0.0f) + l);
}

// ---- kernel 1: total_neg per anchor + init assigned/pcount ----
__global__ void totalneg_kernel(const float* __restrict__ scores) {
    int idx = blockIdx.x * blockDim.x + threadIdx.x;
    if (idx < A_N) g_assigned[idx] = -1;
    if (idx < G_N) g_pcount[idx] = 0;
    int warp = idx >> 5, lane = idx & 31;
    if (warp >= A_N) return;
    float sum = 0.0f;
    for (int c = lane; c < C_N; c += 32) {
        float x = scores[warp * C_N + c];
        sum += fmaxf(x, 0.0f) + log1pf(expf(-fabsf(x)));
    }
    for (int o = 16; o; o >>= 1) sum += __shfl_down_sync(0xffffffffu, sum, o);
    if (lane == 0) g_total_neg[warp] = sum;
}

// ---- kernel 2: pair generation (inside == in_gt since radius 2.5 >= 0.5) ----
__global__ __launch_bounds__(NT) void pairgen_kernel(
    const float* __restrict__ anchor_points,
    const float* __restrict__ gt_bboxes)
{
    __shared__ float4 sgt[G_N];
    int tid = threadIdx.x;
    if (tid < G_N) sgt[tid] = ((const float4*)gt_bboxes)[tid];
    __syncthreads();

    int a = blockIdx.x * NT + tid;
    if (a >= A_N) return;
    float2 ap = ((const float2*)anchor_points)[a];

#pragma unroll 4
    for (int g = 0; g < G_N; g++) {
        float4 b = sgt[g];
        if (ap.x >= b.x && ap.x <= b.z && ap.y >= b.y && ap.y <= b.w) {
            int slot = atomicAdd(&g_pcount[g], 1);
            if (slot < CAP) g_plist[g * CAP + slot] = a;
        }
    }
}

// ---- kernel 3: per-GT cost over candidates, top-10, dyn_k, scatter ----
__global__ __launch_bounds__(NT) void topk_kernel(
    const float* __restrict__ pred_scores,
    const float* __restrict__ pred_bboxes,
    const int*   __restrict__ gt_labels,
    const float* __restrict__ gt_bboxes)
{
    const int g   = blockIdx.x;
    const int tid = threadIdx.x;

    const float4 gb = ((const float4*)gt_bboxes)[g];
    const float gx1 = gb.x, gy1 = gb.y, gx2 = gb.z, gy2 = gb.w;
    const int   L   = gt_labels[g];
    const float area_g = (gx2 - gx1) * (gy2 - gy1);

    const float4* pb4 = (const float4*)pred_bboxes;
    const int n = min(g_pcount[g], CAP);

    __shared__ unsigned long long skeys[NT * TOPK];
    __shared__ unsigned long long swmin[NT / 32];
    __shared__ int scnt[NT / 32];
    __shared__ unsigned long long s_winner;
    __shared__ int s_topk[TOPK];
    __shared__ int s_k;

    const int lane = tid & 31, wid = tid >> 5;

    if (n > 0) {
        // ------- inside candidates: full cost (mask = 0) -------
        unsigned long long bk[TOPK];
#pragma unroll
        for (int j = 0; j < TOPK; j++) bk[j] = SENT;
        int cnt = 0;

        for (int i = tid; i < n; i += NT) {
            int a = g_plist[g * CAP + i];
            float4 pb = __ldg(pb4 + a);
            float w  = fmaxf(fminf(pb.z, gx2) - fmaxf(pb.x, gx1), 0.0f);
            float h  = fmaxf(fminf(pb.w, gy2) - fmaxf(pb.y, gy1), 0.0f);
            float ov = w * h;
            cnt += (ov > 0.0f);
            float area_p = (pb.z - pb.x) * (pb.w - pb.y);
            float iou  = ov / (area_p + area_g - ov + 1e-6f);
            float iouc = -logf(fmaxf(iou, 1e-7f));
            float s    = __ldg(pred_scores + (size_t)a * C_N + L);
            float cls  = g_total_neg[a] + sp_diff(s);
            float cost = __fadd_rn(cls, __fmul_rn(3.0f, iouc));  // +0.0 mask is identity
            unsigned long long k = packKey(cost, (unsigned)a);
            if (k < bk[TOPK - 1]) {
                bk[TOPK - 1] = k;
#pragma unroll
                for (int j = TOPK - 1; j > 0; j--) {
                    bool sw = bk[j] < bk[j - 1];
                    unsigned long long lo = sw ? bk[j] : bk[j - 1];
                    unsigned long long hi = sw ? bk[j - 1] : bk[j];
                    bk[j - 1] = lo; bk[j] = hi;
                }
            }
        }

#pragma unroll
        for (int j = 0; j < TOPK; j++) skeys[tid * TOPK + j] = bk[j];

        int c = cnt;
        for (int o = 16; o; o >>= 1) c += __shfl_down_sync(0xffffffffu, c, o);
        if (lane == 0) scnt[wid] = c;
        __syncthreads();
        if (tid == 0) {
            int s = 0;
            for (int i = 0; i < NT / 32; i++) s += scnt[i];
            s_k = (s < 1) ? 1 : ((s > TOPK) ? TOPK : s);
        }

        int p = 0;
        for (int r = 0; r < TOPK; r++) {
            unsigned long long candk = (p < TOPK) ? skeys[tid * TOPK + p] : SENT;
            unsigned long long m = candk;
            for (int o = 16; o; o >>= 1) {
                unsigned long long other = __shfl_down_sync(0xffffffffu, m, o);
                m = (other < m) ? other : m;
            }
            if (lane == 0) swmin[wid] = m;
            __syncthreads();
            if (tid == 0) {
                unsigned long long w = swmin[0];
                for (int i = 1; i < NT / 32; i++) if (swmin[i] < w) w = swmin[i];
                s_winner = w;
                s_topk[r] = (int)(w & 0xffffffffu);
            }
            __syncthreads();
            if (candk == s_winner) p++;
        }

        // dyn_k <= cnt <= n, and every inside cost < every outside cost,
        // so the global top-dyn_k are exactly these candidates.
        if (tid < s_k) atomicMax(&g_assigned[s_topk[tid]], g);
    } else {
        // ------- zero inside anchors: dyn_k = 1, global argmin (all outside) -------
        unsigned long long best = SENT;
        for (int a = tid; a < A_N; a += NT) {
            float4 pb = __ldg(pb4 + a);
            float w  = fmaxf(fminf(pb.z, gx2) - fmaxf(pb.x, gx1), 0.0f);
            float h  = fmaxf(fminf(pb.w, gy2) - fmaxf(pb.y, gy1), 0.0f);
            float ov = w * h;
            float area_p = (pb.z - pb.x) * (pb.w - pb.y);
            float iou  = ov / (area_p + area_g - ov + 1e-6f);
            float iouc = -logf(fmaxf(iou, 1e-7f));
            float s    = __ldg(pred_scores + (size_t)a * C_N + L);
            float cls  = g_total_neg[a] + sp_diff(s);
            float cost = __fadd_rn(__fadd_rn(cls, __fmul_rn(3.0f, iouc)), 1e10f);
            unsigned long long k = packKey(cost, (unsigned)a);
            if (k < best) best = k;
        }
        for (int o = 16; o; o >>= 1) {
            unsigned long long other = __shfl_down_sync(0xffffffffu, best, o);
            best = (other < best) ? other : best;
        }
        if (lane == 0) swmin[wid] = best;
        __syncthreads();
        if (tid == 0) {
            unsigned long long w = swmin[0];
            for (int i = 1; i < NT / 32; i++) if (swmin[i] < w) w = swmin[i];
            atomicMax(&g_assigned[(int)(w & 0xffffffffu)], g);
        }
    }
}

// ---- kernel 4a: zero the scores region, coalesced float4 ----
__global__ void zero_scores_kernel(float* __restrict__ out) {
    int i = blockIdx.x * blockDim.x + threadIdx.x;
    const int n4 = (A_N * (C_N + 1)) / 4;   // 680400
    float4* p = (float4*)(out + (size_t)5 * A_N);
    if (i < n4) p[i] = make_float4(0.f, 0.f, 0.f, 0.f);
}

// ---- kernel 4b: labels + bboxes + one-hot scatter ----
__global__ void finalize_kernel(const float* __restrict__ pred_bboxes,
                                const int*   __restrict__ gt_labels,
                                const float* __restrict__ gt_bboxes,
                                float* __restrict__ out)
{
    int a = blockIdx.x * blockDim.x + threadIdx.x;
    if (a >= A_N) return;

    int  g    = g_assigned[a];
    bool pos  = (g >= 0);
    int  safe = pos ? g : 0;
    int  label = pos ? gt_labels[safe] : C_N;

    float4 gbx = ((const float4*)gt_bboxes)[safe];

    out[a] = (float)label;

    float4* ob = (float4*)(out + A_N);
    ob[a] = pos ? gbx : make_float4(0.f, 0.f, 0.f, 0.f);

    if (pos) {
        float4 pb = ((const float4*)pred_bboxes)[a];
        float w = fmaxf(fminf(pb.z, gbx.z) - fmaxf(pb.x, gbx.x), 0.0f);
        float h = fmaxf(fminf(pb.w, gbx.w) - fmaxf(pb.y, gbx.y), 0.0f);
        float ov = w * h;
        float area_p = (pb.z - pb.x) * (pb.w - pb.y);
        float area_g = (gbx.z - gbx.x) * (gbx.w - gbx.y);
        float iou = ov / (area_p + area_g - ov + 1e-6f);
        out[(size_t)5 * A_N + (size_t)a * (C_N + 1) + label] = iou;
    }
}

extern "C" void kernel_launch(void* const* d_in, const int* in_sizes, int n_in,
                              void* d_out, int out_size) {
    const float* pred_scores   = (const float*)d_in[0];
    const float* pred_bboxes   = (const float*)d_in[1];
    const float* anchor_points = (const float*)d_in[2];
    const int*   gt_labels     = (const int*)  d_in[3];
    const float* gt_bboxes     = (const float*)d_in[4];
    float* out = (float*)d_out;

    totalneg_kernel<<<(A_N * 32 + 255) / 256, 256>>>(pred_scores);
    zero_scores_kernel<<<((A_N * (C_N + 1)) / 4 + 255) / 256, 256>>>(out);
    pairgen_kernel<<<(A_N + NT - 1) / NT, NT>>>(anchor_points, gt_bboxes);
    topk_kernel<<<G_N, NT>>>(pred_scores, pred_bboxes, gt_labels, gt_bboxes);
    finalize_kernel<<<(A_N + 255) / 256, 256>>>(pred_bboxes, gt_labels, gt_bboxes, out);
}

// round 7
// speedup vs baseline: 3.2595x; 1.7863x over previous
#include <cuda_runtime.h>
#include <math.h>
#include <float.h>

#define A_N 33600
#define G_N 256
#define C_N 80
#define TOPK 10
#define NT   256
#define CAP  4096
#define SENT 0xFFFFFFFFFFFFFFFFULL

// Scratch (allocation-free: __device__ globals)
__device__ float g_total_neg[A_N];
__device__ int   g_assigned[A_N];

// monotone float -> uint mapping, packed with index: lexicographic (cost asc, idx asc)
__device__ __forceinline__ unsigned long long packKey(float v, unsigned idx) {
    unsigned u = __float_as_uint(v);
    u = (u & 0x80000000u) ? ~u : (u | 0x80000000u);
    return (((unsigned long long)u) << 32) | (unsigned long long)idx;
}

// softplus difference with the reference's exact rounding sequence
__device__ __forceinline__ float sp_diff(float s) {
    float l = log1pf(expf(-fabsf(s)));
    return (fmaxf(-s, 0.0f) + l) - (fmaxf(s, 0.0f) + l);
}

// ---- kernel 1: prep = total_neg per anchor + init assigned + zero scores ----
__global__ void prep_kernel(const float* __restrict__ scores, float* __restrict__ out) {
    int idx = blockIdx.x * blockDim.x + threadIdx.x;
    if (idx < A_N) g_assigned[idx] = -1;
    const int n4 = (A_N * (C_N + 1)) / 4;   // 680400 float4s in the scores region
    if (idx < n4)
        ((float4*)(out + (size_t)5 * A_N))[idx] = make_float4(0.f, 0.f, 0.f, 0.f);
    int warp = idx >> 5, lane = idx & 31;
    if (warp >= A_N) return;
    float sum = 0.0f;
    for (int c = lane; c < C_N; c += 32) {
        float x = scores[warp * C_N + c];
        sum += fmaxf(x, 0.0f) + log1pf(expf(-fabsf(x)));
    }
    for (int o = 16; o; o >>= 1) sum += __shfl_down_sync(0xffffffffu, sum, o);
    if (lane == 0) g_total_neg[warp] = sum;
}

// ---- kernel 2: fused per-GT candidate scan + cost + top-10 + dyn_k + scatter ----
__global__ __launch_bounds__(NT) void topk_kernel(
    const float* __restrict__ pred_scores,
    const float* __restrict__ pred_bboxes,
    const float* __restrict__ anchor_points,
    const int*   __restrict__ gt_labels,
    const float* __restrict__ gt_bboxes)
{
    const int g   = blockIdx.x;
    const int tid = threadIdx.x;

    const float4 gb = ((const float4*)gt_bboxes)[g];
    const float gx1 = gb.x, gy1 = gb.y, gx2 = gb.z, gy2 = gb.w;
    const int   L   = gt_labels[g];
    const float area_g = (gx2 - gx1) * (gy2 - gy1);

    const float2* ap2 = (const float2*)anchor_points;
    const float4* pb4 = (const float4*)pred_bboxes;

    __shared__ int s_list[CAP];
    __shared__ int s_n;
    __shared__ unsigned long long skeys[NT * TOPK];
    __shared__ unsigned long long swmin[NT / 32];
    __shared__ int scnt[NT / 32];
    __shared__ unsigned long long s_winner;
    __shared__ int s_topk[TOPK];
    __shared__ int s_k;

    const int lane = tid & 31, wid = tid >> 5;

    if (tid == 0) s_n = 0;
    __syncthreads();

    // ---- phase 1: inside scan (inside == in_gt since radius 2.5 >= 0.5) ----
    for (int a = tid; a < A_N; a += NT) {
        float2 ap = __ldg(ap2 + a);
        if (ap.x >= gx1 && ap.x <= gx2 && ap.y >= gy1 && ap.y <= gy2) {
            int slot = atomicAdd(&s_n, 1);
            if (slot < CAP) s_list[slot] = a;
        }
    }
    __syncthreads();
    const int n = min(s_n, CAP);

    if (n > 0) {
        // ---- phase 2: full cost over candidates (mask = 0 for inside) ----
        unsigned long long bk[TOPK];
#pragma unroll
        for (int j = 0; j < TOPK; j++) bk[j] = SENT;
        int cnt = 0;

        for (int i = tid; i < n; i += NT) {
            int a = s_list[i];
            float4 pb = __ldg(pb4 + a);
            float w  = fmaxf(fminf(pb.z, gx2) - fmaxf(pb.x, gx1), 0.0f);
            float h  = fmaxf(fminf(pb.w, gy2) - fmaxf(pb.y, gy1), 0.0f);
            float ov = w * h;
            cnt += (ov > 0.0f);
            float area_p = (pb.z - pb.x) * (pb.w - pb.y);
            float iou  = ov / (area_p + area_g - ov + 1e-6f);
            float iouc = -logf(fmaxf(iou, 1e-7f));
            float s    = __ldg(pred_scores + (size_t)a * C_N + L);
            float cls  = g_total_neg[a] + sp_diff(s);
            float cost = __fadd_rn(cls, __fmul_rn(3.0f, iouc));
            unsigned long long k = packKey(cost, (unsigned)a);
            if (k < bk[TOPK - 1]) {
                bk[TOPK - 1] = k;
#pragma unroll
                for (int j = TOPK - 1; j > 0; j--) {
                    bool sw = bk[j] < bk[j - 1];
                    unsigned long long lo = sw ? bk[j] : bk[j - 1];
                    unsigned long long hi = sw ? bk[j - 1] : bk[j];
                    bk[j - 1] = lo; bk[j] = hi;
                }
            }
        }

#pragma unroll
        for (int j = 0; j < TOPK; j++) skeys[tid * TOPK + j] = bk[j];

        int c = cnt;
        for (int o = 16; o; o >>= 1) c += __shfl_down_sync(0xffffffffu, c, o);
        if (lane == 0) scnt[wid] = c;
        __syncthreads();
        if (tid == 0) {
            int s = 0;
            for (int i = 0; i < NT / 32; i++) s += scnt[i];
            s_k = (s < 1) ? 1 : ((s > TOPK) ? TOPK : s);
        }

        // ---- phase 3: block merge of sorted per-thread top-10s ----
        int p = 0;
        for (int r = 0; r < TOPK; r++) {
            unsigned long long candk = (p < TOPK) ? skeys[tid * TOPK + p] : SENT;
            unsigned long long m = candk;
            for (int o = 16; o; o >>= 1) {
                unsigned long long other = __shfl_down_sync(0xffffffffu, m, o);
                m = (other < m) ? other : m;
            }
            if (lane == 0) swmin[wid] = m;
            __syncthreads();
            if (tid == 0) {
                unsigned long long w = swmin[0];
                for (int i = 1; i < NT / 32; i++) if (swmin[i] < w) w = swmin[i];
                s_winner = w;
                s_topk[r] = (int)(w & 0xffffffffu);
            }
            __syncthreads();
            if (candk == s_winner) p++;
        }

        // dyn_k <= cnt <= n, and every inside cost < every outside cost,
        // so the global top-dyn_k are exactly these candidates.
        if (tid < s_k) atomicMax(&g_assigned[s_topk[tid]], g);
    } else {
        // ---- zero inside anchors: dyn_k = 1, global argmin (all outside) ----
        unsigned long long best = SENT;
        for (int a = tid; a < A_N; a += NT) {
            float4 pb = __ldg(pb4 + a);
            float w  = fmaxf(fminf(pb.z, gx2) - fmaxf(pb.x, gx1), 0.0f);
            float h  = fmaxf(fminf(pb.w, gy2) - fmaxf(pb.y, gy1), 0.0f);
            float ov = w * h;
            float area_p = (pb.z - pb.x) * (pb.w - pb.y);
            float iou  = ov / (area_p + area_g - ov + 1e-6f);
            float iouc = -logf(fmaxf(iou, 1e-7f));
            float s    = __ldg(pred_scores + (size_t)a * C_N + L);
            float cls  = g_total_neg[a] + sp_diff(s);
            float cost = __fadd_rn(__fadd_rn(cls, __fmul_rn(3.0f, iouc)), 1e10f);
            unsigned long long k = packKey(cost, (unsigned)a);
            if (k < best) best = k;
        }
        for (int o = 16; o; o >>= 1) {
            unsigned long long other = __shfl_down_sync(0xffffffffu, best, o);
            best = (other < best) ? other : best;
        }
        if (lane == 0) swmin[wid] = best;
        __syncthreads();
        if (tid == 0) {
            unsigned long long w = swmin[0];
            for (int i = 1; i < NT / 32; i++) if (swmin[i] < w) w = swmin[i];
            atomicMax(&g_assigned[(int)(w & 0xffffffffu)], g);
        }
    }
}

// ---- kernel 3: labels + bboxes + one-hot scatter (scores pre-zeroed) ----
__global__ void finalize_kernel(const float* __restrict__ pred_bboxes,
                                const int*   __restrict__ gt_labels,
                                const float* __restrict__ gt_bboxes,
                                float* __restrict__ out)
{
    int a = blockIdx.x * blockDim.x + threadIdx.x;
    if (a >= A_N) return;

    int  g    = g_assigned[a];
    bool pos  = (g >= 0);
    int  safe = pos ? g : 0;
    int  label = pos ? gt_labels[safe] : C_N;

    float4 gbx = ((const float4*)gt_bboxes)[safe];

    out[a] = (float)label;

    float4* ob = (float4*)(out + A_N);
    ob[a] = pos ? gbx : make_float4(0.f, 0.f, 0.f, 0.f);

    if (pos) {
        float4 pb = ((const float4*)pred_bboxes)[a];
        float w = fmaxf(fminf(pb.z, gbx.z) - fmaxf(pb.x, gbx.x), 0.0f);
        float h = fmaxf(fminf(pb.w, gbx.w) - fmaxf(pb.y, gbx.y), 0.0f);
        float ov = w * h;
        float area_p = (pb.z - pb.x) * (pb.w - pb.y);
        float area_g = (gbx.z - gbx.x) * (gbx.w - gbx.y);
        float iou = ov / (area_p + area_g - ov + 1e-6f);
        out[(size_t)5 * A_N + (size_t)a * (C_N + 1) + label] = iou;
    }
}

extern "C" void kernel_launch(void* const* d_in, const int* in_sizes, int n_in,
                              void* d_out, int out_size) {
    const float* pred_scores   = (const float*)d_in[0];
    const float* pred_bboxes   = (const float*)d_in[1];
    const float* anchor_points = (const float*)d_in[2];
    const int*   gt_labels     = (const int*)  d_in[3];
    const float* gt_bboxes     = (const float*)d_in[4];
    float* out = (float*)d_out;

    prep_kernel<<<(A_N * 32 + 255) / 256, 256>>>(pred_scores, out);
    topk_kernel<<<G_N, NT>>>(pred_scores, pred_bboxes, anchor_points,
                             gt_labels, gt_bboxes);
    finalize_kernel<<<(A_N + 255) / 256, 256>>>(pred_bboxes, gt_labels, gt_bboxes, out);
}